// round 12
// baseline (speedup 1.0000x reference)
#include <cuda_runtime.h>
#include <math.h>

// Problem constants
#define BB   4096
#define TT   64
#define DD   100
#define FF   50
#define LL   64
#define NUU  64
#define KK   128
#define GII  114   // F + L
#define RB   32    // rows per CTA
#define NTHR 256
#define SPC  34    // col-major stride
#define SYC  116   // YC row-major stride (29 quads * 4)
#define SH2  68    // H/HR row-major stride

// ---- dynamic shared memory layout (floats) ----
#define S_WU1 0
#define S_WR1 (S_WU1 + GII*64)
#define S_WN1 (S_WR1 + GII*64)
#define S_WO1 (S_WN1 + GII*64)
#define S_WU2 (S_WO1 + 64*64)
#define S_WR2 (S_WU2 + 64*64)
#define S_WN2 (S_WR2 + 64*64)
#define S_WO2 (S_WN2 + 64*64)
#define S_WD  (S_WO2 + 64*64)
#define S_BU1 (S_WD + 64)
#define S_BU2 (S_BU1 + 64)
#define S_BR1 (S_BU2 + 64)
#define S_BR2 (S_BR1 + 64)
#define S_BN1 (S_BR2 + 64)
#define S_BN2 (S_BN1 + 64)
#define S_BO1 (S_BN2 + 64)
#define S_BO2 (S_BO1 + 64)
#define S_Y   (S_BO2 + 64)            // col-major 64 x SPC
#define S_H   (S_Y  + 64*SPC)         // o-path H col-major 64xSPC,
                                      // ALIASED as chain H_u row-major 32xSH2
#define S_YC  (S_H  + 64*SPC)         // row-major 32 x SYC
#define S_PV  (S_YC + RB*SYC)         // 8 x 32 vol partials
#define S_ACTB (S_PV + 8*32)          // act table (4096 bytes)
#define S_IDXB (S_ACTB + 1024)        // idx table (4096 bytes)
#define S_HR  (S_IDXB + 1024)         // chain H_r row-major 32 x SH2
#define S_END (S_HR + RB*SH2)
#define SMEM_BYTES (S_END * 4)        // 221952 bytes

typedef unsigned long long u64;

// scratch: per-row per-step volume output
__device__ float g_vol[BB * KK];

// ---- fast math primitives ----
__device__ __forceinline__ float fast_rcp(float x) {
    float r; asm("rcp.approx.f32 %0, %1;" : "=f"(r) : "f"(x)); return r;
}
__device__ __forceinline__ float fast_ex2(float x) {
    float r; asm("ex2.approx.f32 %0, %1;" : "=f"(r) : "f"(x)); return r;
}
__device__ __forceinline__ float fast_sigm(float x) {
    return fast_rcp(1.0f + fast_ex2(-1.4426950408889634f * x));
}
__device__ __forceinline__ float fast_tanh(float x) {
    return fmaf(2.0f, fast_rcp(1.0f + fast_ex2(-2.8853900817779268f * x)), -1.0f);
}

// ---- packed f32x2 primitives ----
__device__ __forceinline__ u64 pack2(float x) {
    u64 r; asm("mov.b64 %0, {%1, %1};" : "=l"(r) : "f"(x)); return r;
}
__device__ __forceinline__ void fma2(u64& d, u64 a, u64 b) {
    asm("fma.rn.f32x2 %0, %1, %2, %0;" : "+l"(d) : "l"(a), "l"(b));
}
__device__ __forceinline__ float2 unpack2(u64 v) {
    float2 f; asm("mov.b64 {%0, %1}, %2;" : "=f"(f.x), "=f"(f.y) : "l"(v)); return f;
}

// All-row GEMM, col-major A (stride SPC): thread = rows (r0,r0+1) x cols [cq,cq+4).
template<int KI>
__device__ __forceinline__ void mmA(const float* __restrict__ A,
                                    const float* __restrict__ W,
                                    int r0, int cq, u64 (&acc)[4]) {
    acc[0] = acc[1] = acc[2] = acc[3] = 0ULL;
#pragma unroll 4
    for (int k = 0; k < KI; ++k) {
        float2 a = *reinterpret_cast<const float2*>(A + k * SPC + r0);
        ulonglong2 w = *reinterpret_cast<const ulonglong2*>(W + k * 64 + cq);
        u64 ax = pack2(a.x), ay = pack2(a.y);
        fma2(acc[0], ax, w.x);
        fma2(acc[1], ax, w.y);
        fma2(acc[2], ay, w.x);
        fma2(acc[3], ay, w.y);
    }
}

// Compacted GEMM, row-major A (stride AS): thread = row ra x cols [cb,cb+4).
template<int NQ, int AS>
__device__ __forceinline__ void mmC(const float* __restrict__ A,
                                    const float* __restrict__ W,
                                    int ra, int cb, u64 (&acc)[2]) {
    acc[0] = acc[1] = 0ULL;
    const float4* ap = reinterpret_cast<const float4*>(A + ra * AS);
#pragma unroll 2
    for (int q = 0; q < NQ; ++q) {
        float4 a4 = ap[q];
        const float* W4 = W + 4 * q * 64 + cb;
        {
            u64 aa = pack2(a4.x);
            ulonglong2 w = *reinterpret_cast<const ulonglong2*>(W4);
            fma2(acc[0], aa, w.x); fma2(acc[1], aa, w.y);
        }
        {
            u64 aa = pack2(a4.y);
            ulonglong2 w = *reinterpret_cast<const ulonglong2*>(W4 + 64);
            fma2(acc[0], aa, w.x); fma2(acc[1], aa, w.y);
        }
        {
            u64 aa = pack2(a4.z);
            ulonglong2 w = *reinterpret_cast<const ulonglong2*>(W4 + 128);
            fma2(acc[0], aa, w.x); fma2(acc[1], aa, w.y);
        }
        {
            u64 aa = pack2(a4.w);
            ulonglong2 w = *reinterpret_cast<const ulonglong2*>(W4 + 192);
            fma2(acc[0], aa, w.x); fma2(acc[1], aa, w.y);
        }
    }
}

// Dual-W compacted GEMM: one A stream, two weight matrices (shared A -> 2x ILP).
template<int NQ, int AS>
__device__ __forceinline__ void mmC2(const float* __restrict__ A,
                                     const float* __restrict__ W1,
                                     const float* __restrict__ W2,
                                     int ra, int cb,
                                     u64 (&accA)[2], u64 (&accB)[2]) {
    accA[0] = accA[1] = 0ULL; accB[0] = accB[1] = 0ULL;
    const float4* ap = reinterpret_cast<const float4*>(A + ra * AS);
#pragma unroll 2
    for (int q = 0; q < NQ; ++q) {
        float4 a4 = ap[q];
        const float* W1q = W1 + 4 * q * 64 + cb;
        const float* W2q = W2 + 4 * q * 64 + cb;
        float av[4] = {a4.x, a4.y, a4.z, a4.w};
#pragma unroll
        for (int s = 0; s < 4; ++s) {
            u64 aa = pack2(av[s]);
            ulonglong2 w1 = *reinterpret_cast<const ulonglong2*>(W1q + s * 64);
            ulonglong2 w2 = *reinterpret_cast<const ulonglong2*>(W2q + s * 64);
            fma2(accA[0], aa, w1.x); fma2(accA[1], aa, w1.y);
            fma2(accB[0], aa, w2.x); fma2(accB[1], aa, w2.y);
        }
    }
}

// Dual-A dual-W compacted GEMM (independent chains interleaved).
template<int NQ, int AS>
__device__ __forceinline__ void mmC2d(const float* __restrict__ A1,
                                      const float* __restrict__ A2,
                                      const float* __restrict__ W1,
                                      const float* __restrict__ W2,
                                      int ra, int cb,
                                      u64 (&accA)[2], u64 (&accB)[2]) {
    accA[0] = accA[1] = 0ULL; accB[0] = accB[1] = 0ULL;
    const float4* ap1 = reinterpret_cast<const float4*>(A1 + ra * AS);
    const float4* ap2 = reinterpret_cast<const float4*>(A2 + ra * AS);
#pragma unroll 2
    for (int q = 0; q < NQ; ++q) {
        float4 a1 = ap1[q];
        float4 a2 = ap2[q];
        const float* W1q = W1 + 4 * q * 64 + cb;
        const float* W2q = W2 + 4 * q * 64 + cb;
        float a1v[4] = {a1.x, a1.y, a1.z, a1.w};
        float a2v[4] = {a2.x, a2.y, a2.z, a2.w};
#pragma unroll
        for (int s = 0; s < 4; ++s) {
            u64 aa1 = pack2(a1v[s]);
            u64 aa2 = pack2(a2v[s]);
            ulonglong2 w1 = *reinterpret_cast<const ulonglong2*>(W1q + s * 64);
            ulonglong2 w2 = *reinterpret_cast<const ulonglong2*>(W2q + s * 64);
            fma2(accA[0], aa1, w1.x); fma2(accA[1], aa1, w1.y);
            fma2(accB[0], aa2, w2.x); fma2(accB[1], aa2, w2.y);
        }
    }
}

#define PAIR_BAR(grp) asm volatile("bar.sync %0, 64;" :: "r"(1 + (grp)) : "memory")

__global__ void __launch_bounds__(NTHR, 1) lobrm_main(
    const float* __restrict__ data, const int* __restrict__ tsteps,
    const float* __restrict__ Wu1, const float* __restrict__ bu1,
    const float* __restrict__ Wu2, const float* __restrict__ bu2,
    const float* __restrict__ Wr1, const float* __restrict__ br1,
    const float* __restrict__ Wr2, const float* __restrict__ br2,
    const float* __restrict__ Wn1, const float* __restrict__ bn1,
    const float* __restrict__ Wn2, const float* __restrict__ bn2,
    const float* __restrict__ Wo1, const float* __restrict__ bo1,
    const float* __restrict__ Wo2, const float* __restrict__ bo2,
    const float* __restrict__ Wd,  const float* __restrict__ bd,
    float* __restrict__ out_prevy,
    float* __restrict__ out_sel,
    float* __restrict__ out_ti)
{
    extern __shared__ float sm[];
    unsigned char* s_act  = reinterpret_cast<unsigned char*>(sm + S_ACTB); // [KK][RB]
    unsigned char* s_idxk = reinterpret_cast<unsigned char*>(sm + S_IDXB); // [KK][RB]
    __shared__ int   s_nact[KK];
    __shared__ int   s_morflag[RB];   // any-mask-nonzero flag (benign race)
    __shared__ int   s_mflag[RB];
    __shared__ float s_bd;

    const int tid = threadIdx.x;
    const int row_base = blockIdx.x * RB;

    // ---- load weights + biases into smem ----
    {
        auto cpy = [&](int off, const float* src, int n) {
            for (int i = tid; i < n; i += NTHR) sm[off + i] = src[i];
        };
        cpy(S_WU1, Wu1, GII*64); cpy(S_WR1, Wr1, GII*64); cpy(S_WN1, Wn1, GII*64);
        cpy(S_WO1, Wo1, 64*64);  cpy(S_WU2, Wu2, 64*64);  cpy(S_WR2, Wr2, 64*64);
        cpy(S_WN2, Wn2, 64*64);  cpy(S_WO2, Wo2, 64*64);
        cpy(S_WD, Wd, 64);
        cpy(S_BU1, bu1, 64); cpy(S_BU2, bu2, 64);
        cpy(S_BR1, br1, 64); cpy(S_BR2, br2, 64);
        cpy(S_BN1, bn1, 64); cpy(S_BN2, bn2, 64);
        cpy(S_BO1, bo1, 64); cpy(S_BO2, bo2, 64);
    }
    if (tid == 0) s_bd = bd[0];

    // zero state Y and YC (incl. k-pad cols 114,115)
    for (int e = tid; e < 64 * SPC; e += NTHR) sm[S_Y + e] = 0.f;
    for (int e = tid; e < RB * SYC; e += NTHR) sm[S_YC + e] = 0.f;

    // ---- warp 0: presence masks, per-step active lists + event indices ----
    if (tid < RB) {
        const int r = tid;
        unsigned m0 = 0, m1 = 0, m2 = 0, m3 = 0;
        const int* tp = tsteps + (size_t)(row_base + r) * TT;
        for (int t = 0; t < TT; ++t) {
            int v = tp[t];           // in [0, 128)
            unsigned bit = 1u << (v & 31);
            int w = v >> 5;
            if (w == 0) m0 |= bit; else if (w == 1) m1 |= bit;
            else if (w == 2) m2 |= bit; else m3 |= bit;
        }
        const unsigned below = (r == 31) ? 0x7fffffffu : ((1u << r) - 1u);
        int c = 0;
        for (int k = 0; k < KK; ++k) {
            unsigned mk = (k < 32) ? m0 : (k < 64) ? m1 : (k < 96) ? m2 : m3;
            int bit = (mk >> (k & 31)) & 1;
            unsigned bal = __ballot_sync(0xffffffffu, bit);
            if (r == 0) s_nact[k] = __popc(bal);
            s_idxk[k * RB + r] = (unsigned char)c;
            if (bit) s_act[k * RB + __popc(bal & below)] = (unsigned char)r;
            c += bit;
        }
        s_morflag[r] = 0;
    }
    __syncthreads();

    const int lane = tid & 31;
    const int wid  = tid >> 5;
    // mmA mapping: rows (r0, r0+1), cols [cq, cq+4)
    const int r0 = 2 * (lane & 15);
    const int cq = 8 * wid + 4 * (lane >> 4);
    // chain mapping: group (2 warps) = 4 rows x 64 cols
    const int group = wid >> 1;
    const int half  = wid & 1;
    const int p  = lane >> 3;       // row slot within group
    const int g  = lane & 7;        // col quad
    const int cb = 32 * half + 4 * g;

    u64 acc4[4];
    u64 accU[2], accR[2];

    for (int k = 0; k < KK; ++k) {
        const int nact = s_nact[k];
        const unsigned char* actk = s_act + k * RB;

        // ================= P1: feat prefetch + vol partial + o1 =================
        const int nel = nact * DD;
        float fv[13];
#pragma unroll
        for (int it = 0; it < 13; ++it) {
            int e = tid + it * NTHR;
            fv[it] = 0.f;
            if (e < nel) {
                int q = e / DD, f = e - q * DD;
                int ra = actk[q];
                int idx = s_idxk[k * RB + ra];
                fv[it] = data[((size_t)(row_base + ra) * TT + idx) * DD + f];
            }
        }
        // vol partials from prev_y
        {
            float pv = 0.f;
#pragma unroll
            for (int i = 0; i < 8; ++i) {
                int ii = wid * 8 + i;
                pv = fmaf(sm[S_Y + ii * SPC + lane], sm[S_WD + ii], pv);
            }
            sm[S_PV + wid * 32 + lane] = pv;
        }
        // o1: H = tanh(Y @ Wo1 + bo1)   (col-major H)
        mmA<64>(sm + S_Y, sm + S_WO1, r0, cq, acc4);
        {
            float2 a0 = unpack2(acc4[0]), a1 = unpack2(acc4[1]);
            float2 b0 = unpack2(acc4[2]), b1 = unpack2(acc4[3]);
            float vr0[4] = {a0.x, a0.y, a1.x, a1.y};
            float vr1[4] = {b0.x, b0.y, b1.x, b1.y};
#pragma unroll
            for (int cc = 0; cc < 4; ++cc) {
                int j = cq + cc; float bj = sm[S_BO1 + j];
                float2 hv = { fast_tanh(vr0[cc] + bj), fast_tanh(vr1[cc] + bj) };
                *reinterpret_cast<float2*>(sm + S_H + j * SPC + r0) = hv;
            }
        }
        // store fetched feat + mask flags (row-major YC)
#pragma unroll
        for (int it = 0; it < 13; ++it) {
            int e = tid + it * NTHR;
            if (e < nel) {
                int q = e / DD, f = e - q * DD;
                int ra = actk[q];
                if (f < FF) sm[S_YC + ra * SYC + 64 + f] = fv[it];
                else if (fv[it] != 0.f) s_morflag[ra] = 1;   // benign race
            }
        }
        __syncthreads();

        // ================= P2: o2 -> y1 for ALL rows + vol finalize =================
        mmA<64>(sm + S_H, sm + S_WO2, r0, cq, acc4);
        {
            float2 a0 = unpack2(acc4[0]), a1 = unpack2(acc4[1]);
            float2 b0 = unpack2(acc4[2]), b1 = unpack2(acc4[3]);
            float vr0[4] = {a0.x, a0.y, a1.x, a1.y};
            float vr1[4] = {b0.x, b0.y, b1.x, b1.y};
            float4 ya, yb;
#pragma unroll
            for (int cc = 0; cc < 4; ++cc) {
                int j = cq + cc; float bj = sm[S_BO2 + j];
                float2 yv = *reinterpret_cast<const float2*>(sm + S_Y + j * SPC + r0);
                float n0 = vr0[cc] + bj + yv.x;
                float n1 = vr1[cc] + bj + yv.y;
                *reinterpret_cast<float2*>(sm + S_Y + j * SPC + r0) = make_float2(n0, n1);
                (&ya.x)[cc] = n0;
                (&yb.x)[cc] = n1;
            }
            *reinterpret_cast<float4*>(sm + S_YC + r0 * SYC + cq)       = ya;
            *reinterpret_cast<float4*>(sm + S_YC + (r0 + 1) * SYC + cq) = yb;
        }
        if (tid < RB) {
            float v = s_bd;
#pragma unroll
            for (int seg = 0; seg < 8; ++seg) v += sm[S_PV + seg * 32 + tid];
            g_vol[(size_t)(row_base + tid) * KK + k] = v;
            s_mflag[tid] = s_morflag[tid];
            s_morflag[tid] = 0;
        }
        __syncthreads();

        // ============ fused compacted chain: (u1|r1), (u2|r2), n1, n2 ============
        for (int base = 0; base < nact; base += 16) {
            const int slot = base + 4 * group + p;
            const bool valid = slot < nact;
            const int ra = actk[slot & 31] & 31;
            const bool wact = (base + 4 * group) < nact;   // pair-uniform
            if (wact) {
                float4 uw, y1q;
                // u1 + r1 fused (shared A = YC row)
                mmC2<29, SYC>(sm + S_YC, sm + S_WU1, sm + S_WR1, ra, cb, accU, accR);
                {
                    float2 u0 = unpack2(accU[0]), u1 = unpack2(accU[1]);
                    float2 rr0 = unpack2(accR[0]), rr1 = unpack2(accR[1]);
                    float4 hu, hr;
                    hu.x = fast_tanh(u0.x + sm[S_BU1 + cb]);
                    hu.y = fast_tanh(u0.y + sm[S_BU1 + cb + 1]);
                    hu.z = fast_tanh(u1.x + sm[S_BU1 + cb + 2]);
                    hu.w = fast_tanh(u1.y + sm[S_BU1 + cb + 3]);
                    hr.x = fast_tanh(rr0.x + sm[S_BR1 + cb]);
                    hr.y = fast_tanh(rr0.y + sm[S_BR1 + cb + 1]);
                    hr.z = fast_tanh(rr1.x + sm[S_BR1 + cb + 2]);
                    hr.w = fast_tanh(rr1.y + sm[S_BR1 + cb + 3]);
                    if (valid) {
                        *reinterpret_cast<float4*>(sm + S_H  + ra * SH2 + cb) = hu;
                        *reinterpret_cast<float4*>(sm + S_HR + ra * SH2 + cb) = hr;
                    }
                }
                PAIR_BAR(group);
                // u2 + r2 fused (independent A streams H_u / H_r); u, y1 -> registers
                mmC2d<16, SH2>(sm + S_H, sm + S_HR, sm + S_WU2, sm + S_WR2,
                               ra, cb, accU, accR);
                {
                    float2 u0 = unpack2(accU[0]), u1 = unpack2(accU[1]);
                    float2 rr0 = unpack2(accR[0]), rr1 = unpack2(accR[1]);
                    uw.x = fast_sigm(u0.x + sm[S_BU2 + cb]);
                    uw.y = fast_sigm(u0.y + sm[S_BU2 + cb + 1]);
                    uw.z = fast_sigm(u1.x + sm[S_BU2 + cb + 2]);
                    uw.w = fast_sigm(u1.y + sm[S_BU2 + cb + 3]);
                    float rg[4] = { fast_sigm(rr0.x + sm[S_BR2 + cb]),
                                    fast_sigm(rr0.y + sm[S_BR2 + cb + 1]),
                                    fast_sigm(rr1.x + sm[S_BR2 + cb + 2]),
                                    fast_sigm(rr1.y + sm[S_BR2 + cb + 3]) };
                    // YC[0:64] still holds y1 here; read own quad, keep in regs
                    y1q = *reinterpret_cast<const float4*>(sm + S_YC + ra * SYC + cb);
                    float4 yc;
                    yc.x = y1q.x * rg[0];
                    yc.y = y1q.y * rg[1];
                    yc.z = y1q.z * rg[2];
                    yc.w = y1q.w * rg[3];
                    if (valid) *reinterpret_cast<float4*>(sm + S_YC + ra * SYC + cb) = yc;
                }
                PAIR_BAR(group);
                // n1: H_u = tanh(YC @ Wn1 + bn1)
                mmC<29, SYC>(sm + S_YC, sm + S_WN1, ra, cb, accU);
                {
                    float2 v0 = unpack2(accU[0]), v1 = unpack2(accU[1]);
                    float4 hw;
                    hw.x = fast_tanh(v0.x + sm[S_BN1 + cb]);
                    hw.y = fast_tanh(v0.y + sm[S_BN1 + cb + 1]);
                    hw.z = fast_tanh(v1.x + sm[S_BN1 + cb + 2]);
                    hw.w = fast_tanh(v1.y + sm[S_BN1 + cb + 3]);
                    if (valid) *reinterpret_cast<float4*>(sm + S_H + ra * SH2 + cb) = hw;
                }
                PAIR_BAR(group);
                // n2 + blend (u and y1 from registers; only write Y when mask set)
                mmC<16, SH2>(sm + S_H, sm + S_WN2, ra, cb, accU);
                {
                    const int mf = s_mflag[ra];
                    float2 v0 = unpack2(accU[0]), v1 = unpack2(accU[1]);
                    float ns[4] = { v0.x + sm[S_BN2 + cb],
                                    v0.y + sm[S_BN2 + cb + 1],
                                    v1.x + sm[S_BN2 + cb + 2],
                                    v1.y + sm[S_BN2 + cb + 3] };
                    float uu[4]  = {uw.x, uw.y, uw.z, uw.w};
                    float y1v[4] = {y1q.x, y1q.y, y1q.z, y1q.w};
#pragma unroll
                    for (int cc = 0; cc < 4; ++cc) {
                        int j = cb + cc;
                        float ny = fmaf(1.f - uu[cc], ns[cc], uu[cc] * y1v[cc]);
                        if (valid && mf) sm[S_Y + j * SPC + ra] = ny;
                    }
                }
            }
        }
        __syncthreads();
    }

    // ---- write final prev_y ----
    for (int e = tid; e < 64 * RB; e += NTHR) {
        int j = e >> 5, r = e & 31;
        out_prevy[(size_t)(row_base + r) * 64 + j] = sm[S_Y + j * SPC + r];
    }

    // ---- fused gather: selected_state + time_intervals for this CTA's rows ----
    // g_vol writes by this CTA are visible after the final __syncthreads above.
    for (int i = tid; i < RB * (TT - 1); i += NTHR) {
        int r = i / (TT - 1);
        int t = i - r * (TT - 1);
        int b = row_base + r;
        int v0 = tsteps[(size_t)b * TT + t];
        int v1 = tsteps[(size_t)b * TT + t + 1];
        int inv = v0 < 0 ? 0 : (v0 > KK - 2 ? KK - 2 : v0);
        out_sel[(size_t)b * (TT - 1) + t] = g_vol[(size_t)b * KK + inv + 1];
        out_ti[(size_t)b * (TT - 1) + t]  = (float)(v1 - v0);
    }
}

extern "C" void kernel_launch(void* const* d_in, const int* in_sizes, int n_in,
                              void* d_out, int out_size) {
    const float* data = (const float*)d_in[0];
    const int*   ts   = (const int*)d_in[1];
    const float* Wu1 = (const float*)d_in[2];
    const float* bu1 = (const float*)d_in[3];
    const float* Wu2 = (const float*)d_in[4];
    const float* bu2 = (const float*)d_in[5];
    const float* Wr1 = (const float*)d_in[6];
    const float* br1 = (const float*)d_in[7];
    const float* Wr2 = (const float*)d_in[8];
    const float* br2 = (const float*)d_in[9];
    const float* Wn1 = (const float*)d_in[10];
    const float* bn1 = (const float*)d_in[11];
    const float* Wn2 = (const float*)d_in[12];
    const float* bn2 = (const float*)d_in[13];
    const float* Wo1 = (const float*)d_in[14];
    const float* bo1 = (const float*)d_in[15];
    const float* Wo2 = (const float*)d_in[16];
    const float* bo2 = (const float*)d_in[17];
    const float* Wd  = (const float*)d_in[18];
    const float* bd  = (const float*)d_in[19];

    float* out = (float*)d_out;
    float* out_prevy = out;                       // B*64
    float* out_sel   = out + (size_t)BB * LL;     // B*63
    float* out_ti    = out_sel + (size_t)BB * (TT - 1);

    cudaFuncSetAttribute(lobrm_main, cudaFuncAttributeMaxDynamicSharedMemorySize,
                         SMEM_BYTES);
    lobrm_main<<<BB / RB, NTHR, SMEM_BYTES>>>(
        data, ts, Wu1, bu1, Wu2, bu2, Wr1, br1, Wr2, br2,
        Wn1, bn1, Wn2, bn2, Wo1, bo1, Wo2, bo2, Wd, bd,
        out_prevy, out_sel, out_ti);
}

// round 13
// speedup vs baseline: 1.6181x; 1.6181x over previous
#include <cuda_runtime.h>
#include <math.h>

// Problem constants
#define BB   4096
#define TT   64
#define DD   100
#define FF   50
#define LL   64
#define NUU  64
#define KK   128
#define GII  114   // F + L
#define RB   32    // rows per CTA
#define NTHR 256
#define SPC  34    // col-major stride
#define SYC  116   // YC row-major stride (29 quads * 4)
#define SH2  68    // H/HR/U2 row-major stride

// ---- dynamic shared memory layout (floats) ----
#define S_WU1 0
#define S_WR1 (S_WU1 + GII*64)
#define S_WN1 (S_WR1 + GII*64)
#define S_WO1 (S_WN1 + GII*64)
#define S_WU2 (S_WO1 + 64*64)
#define S_WR2 (S_WU2 + 64*64)
#define S_WN2 (S_WR2 + 64*64)
#define S_WO2 (S_WN2 + 64*64)
#define S_WD  (S_WO2 + 64*64)
#define S_BU1 (S_WD + 64)
#define S_BU2 (S_BU1 + 64)
#define S_BR1 (S_BU2 + 64)
#define S_BR2 (S_BR1 + 64)
#define S_BN1 (S_BR2 + 64)
#define S_BN2 (S_BN1 + 64)
#define S_BO1 (S_BN2 + 64)
#define S_BO2 (S_BO1 + 64)
#define S_Y   (S_BO2 + 64)            // col-major 64 x SPC
#define S_H   (S_Y  + 64*SPC)         // o-path H col-major 64xSPC,
                                      // ALIASED as chain H_u row-major 32xSH2
#define S_U2  (S_H  + 64*SPC)         // row-major 32 x SH2
#define S_YC  (S_U2 + RB*SH2)         // row-major 32 x SYC
#define S_PV  (S_YC + RB*SYC)         // 8 x 32 vol partials
#define S_ACTB (S_PV + 8*32)          // act table (4096 bytes)
#define S_IDXB (S_ACTB + 1024)        // idx table (4096 bytes)
#define S_HR  (S_IDXB + 1024)         // chain H_r row-major 32 x SH2
#define S_END (S_HR + RB*SH2)
#define SMEM_BYTES (S_END * 4)        // 230656 bytes

typedef unsigned long long u64;

// scratch: per-row per-step volume output
__device__ float g_vol[BB * KK];

// ---- fast math primitives ----
__device__ __forceinline__ float fast_rcp(float x) {
    float r; asm("rcp.approx.f32 %0, %1;" : "=f"(r) : "f"(x)); return r;
}
__device__ __forceinline__ float fast_ex2(float x) {
    float r; asm("ex2.approx.f32 %0, %1;" : "=f"(r) : "f"(x)); return r;
}
__device__ __forceinline__ float fast_sigm(float x) {
    return fast_rcp(1.0f + fast_ex2(-1.4426950408889634f * x));
}
__device__ __forceinline__ float fast_tanh(float x) {
    return fmaf(2.0f, fast_rcp(1.0f + fast_ex2(-2.8853900817779268f * x)), -1.0f);
}

// ---- packed f32x2 primitives ----
__device__ __forceinline__ u64 pack2(float x) {
    u64 r; asm("mov.b64 %0, {%1, %1};" : "=l"(r) : "f"(x)); return r;
}
__device__ __forceinline__ void fma2(u64& d, u64 a, u64 b) {
    asm("fma.rn.f32x2 %0, %1, %2, %0;" : "+l"(d) : "l"(a), "l"(b));
}
__device__ __forceinline__ float2 unpack2(u64 v) {
    float2 f; asm("mov.b64 {%0, %1}, %2;" : "=f"(f.x), "=f"(f.y) : "l"(v)); return f;
}

// All-row GEMM, col-major A (stride SPC): thread = rows (r0,r0+1) x cols [cq,cq+4).
template<int KI>
__device__ __forceinline__ void mmA(const float* __restrict__ A,
                                    const float* __restrict__ W,
                                    int r0, int cq, u64 (&acc)[4]) {
    acc[0] = acc[1] = acc[2] = acc[3] = 0ULL;
#pragma unroll 4
    for (int k = 0; k < KI; ++k) {
        float2 a = *reinterpret_cast<const float2*>(A + k * SPC + r0);
        ulonglong2 w = *reinterpret_cast<const ulonglong2*>(W + k * 64 + cq);
        u64 ax = pack2(a.x), ay = pack2(a.y);
        fma2(acc[0], ax, w.x);
        fma2(acc[1], ax, w.y);
        fma2(acc[2], ay, w.x);
        fma2(acc[3], ay, w.y);
    }
}

// Compacted GEMM, row-major A (stride AS): thread = row ra x cols [cb,cb+4).
template<int NQ, int AS>
__device__ __forceinline__ void mmC(const float* __restrict__ A,
                                    const float* __restrict__ W,
                                    int ra, int cb, u64 (&acc)[2]) {
    acc[0] = acc[1] = 0ULL;
    const float4* ap = reinterpret_cast<const float4*>(A + ra * AS);
#pragma unroll 2
    for (int q = 0; q < NQ; ++q) {
        float4 a4 = ap[q];
        const float* W4 = W + 4 * q * 64 + cb;
        {
            u64 aa = pack2(a4.x);
            ulonglong2 w = *reinterpret_cast<const ulonglong2*>(W4);
            fma2(acc[0], aa, w.x); fma2(acc[1], aa, w.y);
        }
        {
            u64 aa = pack2(a4.y);
            ulonglong2 w = *reinterpret_cast<const ulonglong2*>(W4 + 64);
            fma2(acc[0], aa, w.x); fma2(acc[1], aa, w.y);
        }
        {
            u64 aa = pack2(a4.z);
            ulonglong2 w = *reinterpret_cast<const ulonglong2*>(W4 + 128);
            fma2(acc[0], aa, w.x); fma2(acc[1], aa, w.y);
        }
        {
            u64 aa = pack2(a4.w);
            ulonglong2 w = *reinterpret_cast<const ulonglong2*>(W4 + 192);
            fma2(acc[0], aa, w.x); fma2(acc[1], aa, w.y);
        }
    }
}

// Dual-W compacted GEMM: one A stream, two weight matrices (shared A -> 2x ILP).
template<int NQ, int AS>
__device__ __forceinline__ void mmC2(const float* __restrict__ A,
                                     const float* __restrict__ W1,
                                     const float* __restrict__ W2,
                                     int ra, int cb,
                                     u64 (&accA)[2], u64 (&accB)[2]) {
    accA[0] = accA[1] = 0ULL; accB[0] = accB[1] = 0ULL;
    const float4* ap = reinterpret_cast<const float4*>(A + ra * AS);
#pragma unroll 2
    for (int q = 0; q < NQ; ++q) {
        float4 a4 = ap[q];
        const float* W1q = W1 + 4 * q * 64 + cb;
        const float* W2q = W2 + 4 * q * 64 + cb;
        float av[4] = {a4.x, a4.y, a4.z, a4.w};
#pragma unroll
        for (int s = 0; s < 4; ++s) {
            u64 aa = pack2(av[s]);
            ulonglong2 w1 = *reinterpret_cast<const ulonglong2*>(W1q + s * 64);
            ulonglong2 w2 = *reinterpret_cast<const ulonglong2*>(W2q + s * 64);
            fma2(accA[0], aa, w1.x); fma2(accA[1], aa, w1.y);
            fma2(accB[0], aa, w2.x); fma2(accB[1], aa, w2.y);
        }
    }
}

// Dual-A dual-W compacted GEMM (independent chains interleaved).
template<int NQ, int AS>
__device__ __forceinline__ void mmC2d(const float* __restrict__ A1,
                                      const float* __restrict__ A2,
                                      const float* __restrict__ W1,
                                      const float* __restrict__ W2,
                                      int ra, int cb,
                                      u64 (&accA)[2], u64 (&accB)[2]) {
    accA[0] = accA[1] = 0ULL; accB[0] = accB[1] = 0ULL;
    const float4* ap1 = reinterpret_cast<const float4*>(A1 + ra * AS);
    const float4* ap2 = reinterpret_cast<const float4*>(A2 + ra * AS);
#pragma unroll 2
    for (int q = 0; q < NQ; ++q) {
        float4 a1 = ap1[q];
        float4 a2 = ap2[q];
        const float* W1q = W1 + 4 * q * 64 + cb;
        const float* W2q = W2 + 4 * q * 64 + cb;
        float a1v[4] = {a1.x, a1.y, a1.z, a1.w};
        float a2v[4] = {a2.x, a2.y, a2.z, a2.w};
#pragma unroll
        for (int s = 0; s < 4; ++s) {
            u64 aa1 = pack2(a1v[s]);
            u64 aa2 = pack2(a2v[s]);
            ulonglong2 w1 = *reinterpret_cast<const ulonglong2*>(W1q + s * 64);
            ulonglong2 w2 = *reinterpret_cast<const ulonglong2*>(W2q + s * 64);
            fma2(accA[0], aa1, w1.x); fma2(accA[1], aa1, w1.y);
            fma2(accB[0], aa2, w2.x); fma2(accB[1], aa2, w2.y);
        }
    }
}

#define PAIR_BAR(grp) asm volatile("bar.sync %0, 64;" :: "r"(1 + (grp)) : "memory")

__global__ void __launch_bounds__(NTHR, 1) lobrm_main(
    const float* __restrict__ data, const int* __restrict__ tsteps,
    const float* __restrict__ Wu1, const float* __restrict__ bu1,
    const float* __restrict__ Wu2, const float* __restrict__ bu2,
    const float* __restrict__ Wr1, const float* __restrict__ br1,
    const float* __restrict__ Wr2, const float* __restrict__ br2,
    const float* __restrict__ Wn1, const float* __restrict__ bn1,
    const float* __restrict__ Wn2, const float* __restrict__ bn2,
    const float* __restrict__ Wo1, const float* __restrict__ bo1,
    const float* __restrict__ Wo2, const float* __restrict__ bo2,
    const float* __restrict__ Wd,  const float* __restrict__ bd,
    float* __restrict__ out_prevy,
    float* __restrict__ out_sel,
    float* __restrict__ out_ti)
{
    extern __shared__ float sm[];
    unsigned char* s_act  = reinterpret_cast<unsigned char*>(sm + S_ACTB); // [KK][RB]
    unsigned char* s_idxk = reinterpret_cast<unsigned char*>(sm + S_IDXB); // [KK][RB]
    __shared__ int   s_nact[KK];
    __shared__ int   s_morflag[RB];   // any-mask-nonzero flag (benign race)
    __shared__ int   s_mflag[RB];
    __shared__ float s_bd;

    const int tid = threadIdx.x;
    const int row_base = blockIdx.x * RB;

    // ---- load weights + biases into smem ----
    {
        auto cpy = [&](int off, const float* src, int n) {
            for (int i = tid; i < n; i += NTHR) sm[off + i] = src[i];
        };
        cpy(S_WU1, Wu1, GII*64); cpy(S_WR1, Wr1, GII*64); cpy(S_WN1, Wn1, GII*64);
        cpy(S_WO1, Wo1, 64*64);  cpy(S_WU2, Wu2, 64*64);  cpy(S_WR2, Wr2, 64*64);
        cpy(S_WN2, Wn2, 64*64);  cpy(S_WO2, Wo2, 64*64);
        cpy(S_WD, Wd, 64);
        cpy(S_BU1, bu1, 64); cpy(S_BU2, bu2, 64);
        cpy(S_BR1, br1, 64); cpy(S_BR2, br2, 64);
        cpy(S_BN1, bn1, 64); cpy(S_BN2, bn2, 64);
        cpy(S_BO1, bo1, 64); cpy(S_BO2, bo2, 64);
    }
    if (tid == 0) s_bd = bd[0];

    // zero state Y and YC (incl. k-pad cols 114,115)
    for (int e = tid; e < 64 * SPC; e += NTHR) sm[S_Y + e] = 0.f;
    for (int e = tid; e < RB * SYC; e += NTHR) sm[S_YC + e] = 0.f;

    // ---- warp 0: presence masks, per-step active lists + event indices ----
    if (tid < RB) {
        const int r = tid;
        unsigned m0 = 0, m1 = 0, m2 = 0, m3 = 0;
        const int* tp = tsteps + (size_t)(row_base + r) * TT;
        for (int t = 0; t < TT; ++t) {
            int v = tp[t];           // in [0, 128)
            unsigned bit = 1u << (v & 31);
            int w = v >> 5;
            if (w == 0) m0 |= bit; else if (w == 1) m1 |= bit;
            else if (w == 2) m2 |= bit; else m3 |= bit;
        }
        const unsigned below = (r == 31) ? 0x7fffffffu : ((1u << r) - 1u);
        int c = 0;
        for (int k = 0; k < KK; ++k) {
            unsigned mk = (k < 32) ? m0 : (k < 64) ? m1 : (k < 96) ? m2 : m3;
            int bit = (mk >> (k & 31)) & 1;
            unsigned bal = __ballot_sync(0xffffffffu, bit);
            if (r == 0) s_nact[k] = __popc(bal);
            s_idxk[k * RB + r] = (unsigned char)c;
            if (bit) s_act[k * RB + __popc(bal & below)] = (unsigned char)r;
            c += bit;
        }
        s_morflag[r] = 0;
    }
    __syncthreads();

    const int lane = tid & 31;
    const int wid  = tid >> 5;
    // mmA mapping: rows (r0, r0+1), cols [cq, cq+4)
    const int r0 = 2 * (lane & 15);
    const int cq = 8 * wid + 4 * (lane >> 4);
    // chain mapping: group (2 warps) = 4 rows x 64 cols
    const int group = wid >> 1;
    const int half  = wid & 1;
    const int p  = lane >> 3;       // row slot within group
    const int g  = lane & 7;        // col quad
    const int cb = 32 * half + 4 * g;

    u64 acc4[4];
    u64 accU[2], accR[2];

    for (int k = 0; k < KK; ++k) {
        const int nact = s_nact[k];
        const unsigned char* actk = s_act + k * RB;

        // ================= P1: feat prefetch + vol partial + o1 =================
        const int nel = nact * DD;
        float fv[13];
#pragma unroll
        for (int it = 0; it < 13; ++it) {
            int e = tid + it * NTHR;
            fv[it] = 0.f;
            if (e < nel) {
                int q = e / DD, f = e - q * DD;
                int ra = actk[q];
                int idx = s_idxk[k * RB + ra];
                fv[it] = data[((size_t)(row_base + ra) * TT + idx) * DD + f];
            }
        }
        // vol partials from prev_y
        {
            float pv = 0.f;
#pragma unroll
            for (int i = 0; i < 8; ++i) {
                int ii = wid * 8 + i;
                pv = fmaf(sm[S_Y + ii * SPC + lane], sm[S_WD + ii], pv);
            }
            sm[S_PV + wid * 32 + lane] = pv;
        }
        // o1: H = tanh(Y @ Wo1 + bo1)   (col-major H)
        mmA<64>(sm + S_Y, sm + S_WO1, r0, cq, acc4);
        {
            float2 a0 = unpack2(acc4[0]), a1 = unpack2(acc4[1]);
            float2 b0 = unpack2(acc4[2]), b1 = unpack2(acc4[3]);
            float vr0[4] = {a0.x, a0.y, a1.x, a1.y};
            float vr1[4] = {b0.x, b0.y, b1.x, b1.y};
#pragma unroll
            for (int cc = 0; cc < 4; ++cc) {
                int j = cq + cc; float bj = sm[S_BO1 + j];
                float2 hv = { fast_tanh(vr0[cc] + bj), fast_tanh(vr1[cc] + bj) };
                *reinterpret_cast<float2*>(sm + S_H + j * SPC + r0) = hv;
            }
        }
        // store fetched feat + mask flags (row-major YC)
#pragma unroll
        for (int it = 0; it < 13; ++it) {
            int e = tid + it * NTHR;
            if (e < nel) {
                int q = e / DD, f = e - q * DD;
                int ra = actk[q];
                if (f < FF) sm[S_YC + ra * SYC + 64 + f] = fv[it];
                else if (fv[it] != 0.f) s_morflag[ra] = 1;   // benign race
            }
        }
        __syncthreads();

        // ================= P2: o2 -> y1 for ALL rows + vol finalize =================
        mmA<64>(sm + S_H, sm + S_WO2, r0, cq, acc4);
        {
            float2 a0 = unpack2(acc4[0]), a1 = unpack2(acc4[1]);
            float2 b0 = unpack2(acc4[2]), b1 = unpack2(acc4[3]);
            float vr0[4] = {a0.x, a0.y, a1.x, a1.y};
            float vr1[4] = {b0.x, b0.y, b1.x, b1.y};
#pragma unroll
            for (int cc = 0; cc < 4; ++cc) {
                int j = cq + cc; float bj = sm[S_BO2 + j];
                float2 yv = *reinterpret_cast<const float2*>(sm + S_Y + j * SPC + r0);
                float n0 = vr0[cc] + bj + yv.x;
                float n1 = vr1[cc] + bj + yv.y;
                *reinterpret_cast<float2*>(sm + S_Y + j * SPC + r0) = make_float2(n0, n1);
                sm[S_YC + r0 * SYC + j]       = n0;
                sm[S_YC + (r0 + 1) * SYC + j] = n1;
            }
        }
        if (tid < RB) {
            float v = s_bd;
#pragma unroll
            for (int seg = 0; seg < 8; ++seg) v += sm[S_PV + seg * 32 + tid];
            g_vol[(size_t)(row_base + tid) * KK + k] = v;
            s_mflag[tid] = s_morflag[tid];
            s_morflag[tid] = 0;
        }
        __syncthreads();

        // ============ fused compacted chain: (u1|r1), (u2|r2), n1, n2 ============
        for (int base = 0; base < nact; base += 16) {
            const int slot = base + 4 * group + p;
            const bool valid = slot < nact;
            const int ra = actk[slot & 31] & 31;
            const bool wact = (base + 4 * group) < nact;   // pair-uniform
            if (wact) {
                // u1 + r1 fused (shared A = YC row)
                mmC2<29, SYC>(sm + S_YC, sm + S_WU1, sm + S_WR1, ra, cb, accU, accR);
                {
                    float2 u0 = unpack2(accU[0]), u1 = unpack2(accU[1]);
                    float2 rr0 = unpack2(accR[0]), rr1 = unpack2(accR[1]);
                    float4 hu, hr;
                    hu.x = fast_tanh(u0.x + sm[S_BU1 + cb]);
                    hu.y = fast_tanh(u0.y + sm[S_BU1 + cb + 1]);
                    hu.z = fast_tanh(u1.x + sm[S_BU1 + cb + 2]);
                    hu.w = fast_tanh(u1.y + sm[S_BU1 + cb + 3]);
                    hr.x = fast_tanh(rr0.x + sm[S_BR1 + cb]);
                    hr.y = fast_tanh(rr0.y + sm[S_BR1 + cb + 1]);
                    hr.z = fast_tanh(rr1.x + sm[S_BR1 + cb + 2]);
                    hr.w = fast_tanh(rr1.y + sm[S_BR1 + cb + 3]);
                    if (valid) {
                        *reinterpret_cast<float4*>(sm + S_H  + ra * SH2 + cb) = hu;
                        *reinterpret_cast<float4*>(sm + S_HR + ra * SH2 + cb) = hr;
                    }
                }
                PAIR_BAR(group);
                // u2 + r2 fused (independent A streams H_u / H_r)
                mmC2d<16, SH2>(sm + S_H, sm + S_HR, sm + S_WU2, sm + S_WR2,
                               ra, cb, accU, accR);
                {
                    float2 u0 = unpack2(accU[0]), u1 = unpack2(accU[1]);
                    float2 rr0 = unpack2(accR[0]), rr1 = unpack2(accR[1]);
                    float4 uw;
                    uw.x = fast_sigm(u0.x + sm[S_BU2 + cb]);
                    uw.y = fast_sigm(u0.y + sm[S_BU2 + cb + 1]);
                    uw.z = fast_sigm(u1.x + sm[S_BU2 + cb + 2]);
                    uw.w = fast_sigm(u1.y + sm[S_BU2 + cb + 3]);
                    float rg[4] = { fast_sigm(rr0.x + sm[S_BR2 + cb]),
                                    fast_sigm(rr0.y + sm[S_BR2 + cb + 1]),
                                    fast_sigm(rr1.x + sm[S_BR2 + cb + 2]),
                                    fast_sigm(rr1.y + sm[S_BR2 + cb + 3]) };
                    float4 yc;
                    yc.x = sm[S_Y + (cb    ) * SPC + ra] * rg[0];
                    yc.y = sm[S_Y + (cb + 1) * SPC + ra] * rg[1];
                    yc.z = sm[S_Y + (cb + 2) * SPC + ra] * rg[2];
                    yc.w = sm[S_Y + (cb + 3) * SPC + ra] * rg[3];
                    if (valid) {
                        *reinterpret_cast<float4*>(sm + S_U2 + ra * SH2 + cb) = uw;
                        *reinterpret_cast<float4*>(sm + S_YC + ra * SYC + cb) = yc;
                    }
                }
                PAIR_BAR(group);
                // n1: H_u = tanh(YC @ Wn1 + bn1)
                mmC<29, SYC>(sm + S_YC, sm + S_WN1, ra, cb, accU);
                {
                    float2 v0 = unpack2(accU[0]), v1 = unpack2(accU[1]);
                    float4 hw;
                    hw.x = fast_tanh(v0.x + sm[S_BN1 + cb]);
                    hw.y = fast_tanh(v0.y + sm[S_BN1 + cb + 1]);
                    hw.z = fast_tanh(v1.x + sm[S_BN1 + cb + 2]);
                    hw.w = fast_tanh(v1.y + sm[S_BN1 + cb + 3]);
                    if (valid) *reinterpret_cast<float4*>(sm + S_H + ra * SH2 + cb) = hw;
                }
                PAIR_BAR(group);
                // n2 + blend (only overwrite Y when mask flag set; else keep y1)
                mmC<16, SH2>(sm + S_H, sm + S_WN2, ra, cb, accU);
                {
                    const int mf = s_mflag[ra];
                    float2 v0 = unpack2(accU[0]), v1 = unpack2(accU[1]);
                    float ns[4] = { v0.x + sm[S_BN2 + cb],
                                    v0.y + sm[S_BN2 + cb + 1],
                                    v1.x + sm[S_BN2 + cb + 2],
                                    v1.y + sm[S_BN2 + cb + 3] };
                    float4 uq = *reinterpret_cast<const float4*>(sm + S_U2 + ra * SH2 + cb);
                    float uu[4] = {uq.x, uq.y, uq.z, uq.w};
#pragma unroll
                    for (int cc = 0; cc < 4; ++cc) {
                        int j = cb + cc;
                        float y1 = sm[S_Y + j * SPC + ra];
                        float ny = fmaf(1.f - uu[cc], ns[cc], uu[cc] * y1);
                        if (valid && mf) sm[S_Y + j * SPC + ra] = ny;
                    }
                }
            }
        }
        __syncthreads();
    }

    // ---- write final prev_y ----
    for (int e = tid; e < 64 * RB; e += NTHR) {
        int j = e >> 5, r = e & 31;
        out_prevy[(size_t)(row_base + r) * 64 + j] = sm[S_Y + j * SPC + r];
    }

    // ---- fused gather: selected_state + time_intervals for this CTA's rows ----
    // g_vol writes by this CTA are visible after the final __syncthreads above.
    for (int i = tid; i < RB * (TT - 1); i += NTHR) {
        int r = i / (TT - 1);
        int t = i - r * (TT - 1);
        int b = row_base + r;
        int v0 = tsteps[(size_t)b * TT + t];
        int v1 = tsteps[(size_t)b * TT + t + 1];
        int inv = v0 < 0 ? 0 : (v0 > KK - 2 ? KK - 2 : v0);
        out_sel[(size_t)b * (TT - 1) + t] = g_vol[(size_t)b * KK + inv + 1];
        out_ti[(size_t)b * (TT - 1) + t]  = (float)(v1 - v0);
    }
}

extern "C" void kernel_launch(void* const* d_in, const int* in_sizes, int n_in,
                              void* d_out, int out_size) {
    const float* data = (const float*)d_in[0];
    const int*   ts   = (const int*)d_in[1];
    const float* Wu1 = (const float*)d_in[2];
    const float* bu1 = (const float*)d_in[3];
    const float* Wu2 = (const float*)d_in[4];
    const float* bu2 = (const float*)d_in[5];
    const float* Wr1 = (const float*)d_in[6];
    const float* br1 = (const float*)d_in[7];
    const float* Wr2 = (const float*)d_in[8];
    const float* br2 = (const float*)d_in[9];
    const float* Wn1 = (const float*)d_in[10];
    const float* bn1 = (const float*)d_in[11];
    const float* Wn2 = (const float*)d_in[12];
    const float* bn2 = (const float*)d_in[13];
    const float* Wo1 = (const float*)d_in[14];
    const float* bo1 = (const float*)d_in[15];
    const float* Wo2 = (const float*)d_in[16];
    const float* bo2 = (const float*)d_in[17];
    const float* Wd  = (const float*)d_in[18];
    const float* bd  = (const float*)d_in[19];

    float* out = (float*)d_out;
    float* out_prevy = out;                       // B*64
    float* out_sel   = out + (size_t)BB * LL;     // B*63
    float* out_ti    = out_sel + (size_t)BB * (TT - 1);

    cudaFuncSetAttribute(lobrm_main, cudaFuncAttributeMaxDynamicSharedMemorySize,
                         SMEM_BYTES);
    lobrm_main<<<BB / RB, NTHR, SMEM_BYTES>>>(
        data, ts, Wu1, bu1, Wu2, bu2, Wr1, br1, Wr2, br2,
        Wn1, bn1, Wn2, bn2, Wo1, bo1, Wo2, bo2, Wd, bd,
        out_prevy, out_sel, out_ti);
}

// round 17
// speedup vs baseline: 1.6775x; 1.0367x over previous
#include <cuda_runtime.h>
#include <math.h>

// Problem constants
#define BB   4096
#define TT   64
#define DD   100
#define FF   50
#define LL   64
#define NUU  64
#define KK   128
#define GII  114   // F + L
#define RB   32    // rows per CTA
#define NTHR 256
#define SPC  34    // col-major stride
#define SYC  116   // YC row-major stride (29 quads * 4)
#define SH2  68    // H/HR row-major stride

// ---- dynamic shared memory layout (floats) ----
#define S_WU1 0
#define S_WR1 (S_WU1 + GII*64)
#define S_WN1 (S_WR1 + GII*64)
#define S_WO1 (S_WN1 + GII*64)
#define S_WU2 (S_WO1 + 64*64)
#define S_WR2 (S_WU2 + 64*64)
#define S_WN2 (S_WR2 + 64*64)
#define S_WO2 (S_WN2 + 64*64)
#define S_WD  (S_WO2 + 64*64)
#define S_BU1 (S_WD + 64)
#define S_BU2 (S_BU1 + 64)
#define S_BR1 (S_BU2 + 64)
#define S_BR2 (S_BR1 + 64)
#define S_BN1 (S_BR2 + 64)
#define S_BN2 (S_BN1 + 64)
#define S_BO1 (S_BN2 + 64)
#define S_BO2 (S_BO1 + 64)
#define S_Y   (S_BO2 + 64)            // col-major 64 x SPC
#define S_H   (S_Y  + 64*SPC)         // o-path H col-major 64xSPC,
                                      // ALIASED as chain H_u row-major 32xSH2
#define S_YC  (S_H  + 64*SPC)         // row-major 32 x SYC
#define S_PV  (S_YC + RB*SYC)         // 8 x 32 vol partials
#define S_ACTB (S_PV + 8*32)          // act table (4096 bytes)
#define S_IDXB (S_ACTB + 1024)        // idx table (4096 bytes)
#define S_HR  (S_IDXB + 1024)         // chain H_r row-major 32 x SH2
#define S_END (S_HR + RB*SH2)
#define SMEM_BYTES (S_END * 4)        // 221952 bytes

typedef unsigned long long u64;

// scratch: per-row per-step volume output
__device__ float g_vol[BB * KK];

// ---- fast math primitives ----
__device__ __forceinline__ float fast_rcp(float x) {
    float r; asm("rcp.approx.f32 %0, %1;" : "=f"(r) : "f"(x)); return r;
}
__device__ __forceinline__ float fast_ex2(float x) {
    float r; asm("ex2.approx.f32 %0, %1;" : "=f"(r) : "f"(x)); return r;
}
__device__ __forceinline__ float fast_sigm(float x) {
    return fast_rcp(1.0f + fast_ex2(-1.4426950408889634f * x));
}
__device__ __forceinline__ float fast_tanh(float x) {
    return fmaf(2.0f, fast_rcp(1.0f + fast_ex2(-2.8853900817779268f * x)), -1.0f);
}

// ---- packed f32x2 primitives ----
__device__ __forceinline__ u64 pack2(float x) {
    u64 r; asm("mov.b64 %0, {%1, %1};" : "=l"(r) : "f"(x)); return r;
}
__device__ __forceinline__ void fma2(u64& d, u64 a, u64 b) {
    asm("fma.rn.f32x2 %0, %1, %2, %0;" : "+l"(d) : "l"(a), "l"(b));
}
__device__ __forceinline__ float2 unpack2(u64 v) {
    float2 f; asm("mov.b64 {%0, %1}, %2;" : "=f"(f.x), "=f"(f.y) : "l"(v)); return f;
}

// All-row GEMM, col-major A (stride SPC): thread = rows (r0,r0+1) x cols [cq,cq+4).
template<int KI>
__device__ __forceinline__ void mmA(const float* __restrict__ A,
                                    const float* __restrict__ W,
                                    int r0, int cq, u64 (&acc)[4]) {
    acc[0] = acc[1] = acc[2] = acc[3] = 0ULL;
#pragma unroll 4
    for (int k = 0; k < KI; ++k) {
        float2 a = *reinterpret_cast<const float2*>(A + k * SPC + r0);
        ulonglong2 w = *reinterpret_cast<const ulonglong2*>(W + k * 64 + cq);
        u64 ax = pack2(a.x), ay = pack2(a.y);
        fma2(acc[0], ax, w.x);
        fma2(acc[1], ax, w.y);
        fma2(acc[2], ay, w.x);
        fma2(acc[3], ay, w.y);
    }
}

// Compacted GEMM, row-major A (stride AS): thread = row ra x cols [cb,cb+4).
template<int NQ, int AS>
__device__ __forceinline__ void mmC(const float* __restrict__ A,
                                    const float* __restrict__ W,
                                    int ra, int cb, u64 (&acc)[2]) {
    acc[0] = acc[1] = 0ULL;
    const float4* ap = reinterpret_cast<const float4*>(A + ra * AS);
#pragma unroll 2
    for (int q = 0; q < NQ; ++q) {
        float4 a4 = ap[q];
        const float* W4 = W + 4 * q * 64 + cb;
        {
            u64 aa = pack2(a4.x);
            ulonglong2 w = *reinterpret_cast<const ulonglong2*>(W4);
            fma2(acc[0], aa, w.x); fma2(acc[1], aa, w.y);
        }
        {
            u64 aa = pack2(a4.y);
            ulonglong2 w = *reinterpret_cast<const ulonglong2*>(W4 + 64);
            fma2(acc[0], aa, w.x); fma2(acc[1], aa, w.y);
        }
        {
            u64 aa = pack2(a4.z);
            ulonglong2 w = *reinterpret_cast<const ulonglong2*>(W4 + 128);
            fma2(acc[0], aa, w.x); fma2(acc[1], aa, w.y);
        }
        {
            u64 aa = pack2(a4.w);
            ulonglong2 w = *reinterpret_cast<const ulonglong2*>(W4 + 192);
            fma2(acc[0], aa, w.x); fma2(acc[1], aa, w.y);
        }
    }
}

// Dual-W compacted GEMM: one A stream, two weight matrices (shared A -> 2x ILP).
template<int NQ, int AS>
__device__ __forceinline__ void mmC2(const float* __restrict__ A,
                                     const float* __restrict__ W1,
                                     const float* __restrict__ W2,
                                     int ra, int cb,
                                     u64 (&accA)[2], u64 (&accB)[2]) {
    accA[0] = accA[1] = 0ULL; accB[0] = accB[1] = 0ULL;
    const float4* ap = reinterpret_cast<const float4*>(A + ra * AS);
#pragma unroll 2
    for (int q = 0; q < NQ; ++q) {
        float4 a4 = ap[q];
        const float* W1q = W1 + 4 * q * 64 + cb;
        const float* W2q = W2 + 4 * q * 64 + cb;
        float av[4] = {a4.x, a4.y, a4.z, a4.w};
#pragma unroll
        for (int s = 0; s < 4; ++s) {
            u64 aa = pack2(av[s]);
            ulonglong2 w1 = *reinterpret_cast<const ulonglong2*>(W1q + s * 64);
            ulonglong2 w2 = *reinterpret_cast<const ulonglong2*>(W2q + s * 64);
            fma2(accA[0], aa, w1.x); fma2(accA[1], aa, w1.y);
            fma2(accB[0], aa, w2.x); fma2(accB[1], aa, w2.y);
        }
    }
}

// Dual-A dual-W compacted GEMM (independent chains interleaved).
template<int NQ, int AS>
__device__ __forceinline__ void mmC2d(const float* __restrict__ A1,
                                      const float* __restrict__ A2,
                                      const float* __restrict__ W1,
                                      const float* __restrict__ W2,
                                      int ra, int cb,
                                      u64 (&accA)[2], u64 (&accB)[2]) {
    accA[0] = accA[1] = 0ULL; accB[0] = accB[1] = 0ULL;
    const float4* ap1 = reinterpret_cast<const float4*>(A1 + ra * AS);
    const float4* ap2 = reinterpret_cast<const float4*>(A2 + ra * AS);
#pragma unroll 2
    for (int q = 0; q < NQ; ++q) {
        float4 a1 = ap1[q];
        float4 a2 = ap2[q];
        const float* W1q = W1 + 4 * q * 64 + cb;
        const float* W2q = W2 + 4 * q * 64 + cb;
        float a1v[4] = {a1.x, a1.y, a1.z, a1.w};
        float a2v[4] = {a2.x, a2.y, a2.z, a2.w};
#pragma unroll
        for (int s = 0; s < 4; ++s) {
            u64 aa1 = pack2(a1v[s]);
            u64 aa2 = pack2(a2v[s]);
            ulonglong2 w1 = *reinterpret_cast<const ulonglong2*>(W1q + s * 64);
            ulonglong2 w2 = *reinterpret_cast<const ulonglong2*>(W2q + s * 64);
            fma2(accA[0], aa1, w1.x); fma2(accA[1], aa1, w1.y);
            fma2(accB[0], aa2, w2.x); fma2(accB[1], aa2, w2.y);
        }
    }
}

__global__ void __launch_bounds__(NTHR, 1) lobrm_main(
    const float* __restrict__ data, const int* __restrict__ tsteps,
    const float* __restrict__ Wu1, const float* __restrict__ bu1,
    const float* __restrict__ Wu2, const float* __restrict__ bu2,
    const float* __restrict__ Wr1, const float* __restrict__ br1,
    const float* __restrict__ Wr2, const float* __restrict__ br2,
    const float* __restrict__ Wn1, const float* __restrict__ bn1,
    const float* __restrict__ Wn2, const float* __restrict__ bn2,
    const float* __restrict__ Wo1, const float* __restrict__ bo1,
    const float* __restrict__ Wo2, const float* __restrict__ bo2,
    const float* __restrict__ Wd,  const float* __restrict__ bd,
    float* __restrict__ out_prevy,
    float* __restrict__ out_sel,
    float* __restrict__ out_ti)
{
    extern __shared__ float sm[];
    unsigned char* s_act  = reinterpret_cast<unsigned char*>(sm + S_ACTB); // [KK][RB]
    unsigned char* s_idxk = reinterpret_cast<unsigned char*>(sm + S_IDXB); // [KK][RB]
    __shared__ int   s_nact[KK];
    __shared__ int   s_morflag[RB];   // any-mask-nonzero flag (benign race)
    __shared__ int   s_mflag[RB];
    __shared__ float s_bd;

    const int tid = threadIdx.x;
    const int row_base = blockIdx.x * RB;

    // ---- load weights + biases into smem ----
    {
        auto cpy = [&](int off, const float* src, int n) {
            for (int i = tid; i < n; i += NTHR) sm[off + i] = src[i];
        };
        cpy(S_WU1, Wu1, GII*64); cpy(S_WR1, Wr1, GII*64); cpy(S_WN1, Wn1, GII*64);
        cpy(S_WO1, Wo1, 64*64);  cpy(S_WU2, Wu2, 64*64);  cpy(S_WR2, Wr2, 64*64);
        cpy(S_WN2, Wn2, 64*64);  cpy(S_WO2, Wo2, 64*64);
        cpy(S_WD, Wd, 64);
        cpy(S_BU1, bu1, 64); cpy(S_BU2, bu2, 64);
        cpy(S_BR1, br1, 64); cpy(S_BR2, br2, 64);
        cpy(S_BN1, bn1, 64); cpy(S_BN2, bn2, 64);
        cpy(S_BO1, bo1, 64); cpy(S_BO2, bo2, 64);
    }
    if (tid == 0) s_bd = bd[0];

    // zero state Y and YC (incl. k-pad cols 114,115)
    for (int e = tid; e < 64 * SPC; e += NTHR) sm[S_Y + e] = 0.f;
    for (int e = tid; e < RB * SYC; e += NTHR) sm[S_YC + e] = 0.f;

    // ---- warp 0: presence masks, per-step active lists + event indices ----
    if (tid < RB) {
        const int r = tid;
        unsigned m0 = 0, m1 = 0, m2 = 0, m3 = 0;
        const int* tp = tsteps + (size_t)(row_base + r) * TT;
        for (int t = 0; t < TT; ++t) {
            int v = tp[t];           // in [0, 128)
            unsigned bit = 1u << (v & 31);
            int w = v >> 5;
            if (w == 0) m0 |= bit; else if (w == 1) m1 |= bit;
            else if (w == 2) m2 |= bit; else m3 |= bit;
        }
        const unsigned below = (r == 31) ? 0x7fffffffu : ((1u << r) - 1u);
        int c = 0;
        for (int k = 0; k < KK; ++k) {
            unsigned mk = (k < 32) ? m0 : (k < 64) ? m1 : (k < 96) ? m2 : m3;
            int bit = (mk >> (k & 31)) & 1;
            unsigned bal = __ballot_sync(0xffffffffu, bit);
            if (r == 0) s_nact[k] = __popc(bal);
            s_idxk[k * RB + r] = (unsigned char)c;
            if (bit) s_act[k * RB + __popc(bal & below)] = (unsigned char)r;
            c += bit;
        }
        s_morflag[r] = 0;
    }
    __syncthreads();

    const int lane = tid & 31;
    const int wid  = tid >> 5;
    // mmA mapping: rows (r0, r0+1), cols [cq, cq+4)
    const int r0 = 2 * (lane & 15);
    const int cq = 8 * wid + 4 * (lane >> 4);
    // chain mapping: warp owns 2 compacted rows end-to-end;
    // lane = (row-half p, col-quad): 1 row x 4 cols of the full 64-col span.
    const int p    = lane >> 4;          // 0/1 row within warp
    const int cb4  = 4 * (lane & 15);    // 0..60

    u64 acc4[4];
    u64 accU[2], accR[2];

    for (int k = 0; k < KK; ++k) {
        const int nact = s_nact[k];
        const unsigned char* actk = s_act + k * RB;

        // ================= P1: feat prefetch + vol partial + o1 =================
        const int nel = nact * DD;
        float fv[13];
#pragma unroll
        for (int it = 0; it < 13; ++it) {
            int e = tid + it * NTHR;
            fv[it] = 0.f;
            if (e < nel) {
                int q = e / DD, f = e - q * DD;
                int ra = actk[q];
                int idx = s_idxk[k * RB + ra];
                fv[it] = data[((size_t)(row_base + ra) * TT + idx) * DD + f];
            }
        }
        // vol partials from prev_y
        {
            float pv = 0.f;
#pragma unroll
            for (int i = 0; i < 8; ++i) {
                int ii = wid * 8 + i;
                pv = fmaf(sm[S_Y + ii * SPC + lane], sm[S_WD + ii], pv);
            }
            sm[S_PV + wid * 32 + lane] = pv;
        }
        // o1: H = tanh(Y @ Wo1 + bo1)   (col-major H)
        mmA<64>(sm + S_Y, sm + S_WO1, r0, cq, acc4);
        {
            float2 a0 = unpack2(acc4[0]), a1 = unpack2(acc4[1]);
            float2 b0 = unpack2(acc4[2]), b1 = unpack2(acc4[3]);
            float vr0[4] = {a0.x, a0.y, a1.x, a1.y};
            float vr1[4] = {b0.x, b0.y, b1.x, b1.y};
#pragma unroll
            for (int cc = 0; cc < 4; ++cc) {
                int j = cq + cc; float bj = sm[S_BO1 + j];
                float2 hv = { fast_tanh(vr0[cc] + bj), fast_tanh(vr1[cc] + bj) };
                *reinterpret_cast<float2*>(sm + S_H + j * SPC + r0) = hv;
            }
        }
        // store fetched feat + mask flags (row-major YC)
#pragma unroll
        for (int it = 0; it < 13; ++it) {
            int e = tid + it * NTHR;
            if (e < nel) {
                int q = e / DD, f = e - q * DD;
                int ra = actk[q];
                if (f < FF) sm[S_YC + ra * SYC + 64 + f] = fv[it];
                else if (fv[it] != 0.f) s_morflag[ra] = 1;   // benign race
            }
        }
        __syncthreads();

        // ================= P2: o2 -> y1 for ALL rows + vol finalize =================
        mmA<64>(sm + S_H, sm + S_WO2, r0, cq, acc4);
        {
            float2 a0 = unpack2(acc4[0]), a1 = unpack2(acc4[1]);
            float2 b0 = unpack2(acc4[2]), b1 = unpack2(acc4[3]);
            float vr0[4] = {a0.x, a0.y, a1.x, a1.y};
            float vr1[4] = {b0.x, b0.y, b1.x, b1.y};
#pragma unroll
            for (int cc = 0; cc < 4; ++cc) {
                int j = cq + cc; float bj = sm[S_BO2 + j];
                float2 yv = *reinterpret_cast<const float2*>(sm + S_Y + j * SPC + r0);
                float n0 = vr0[cc] + bj + yv.x;
                float n1 = vr1[cc] + bj + yv.y;
                *reinterpret_cast<float2*>(sm + S_Y + j * SPC + r0) = make_float2(n0, n1);
                sm[S_YC + r0 * SYC + j]       = n0;
                sm[S_YC + (r0 + 1) * SYC + j] = n1;
            }
        }
        if (tid < RB) {
            float v = s_bd;
#pragma unroll
            for (int seg = 0; seg < 8; ++seg) v += sm[S_PV + seg * 32 + tid];
            g_vol[(size_t)(row_base + tid) * KK + k] = v;
            s_mflag[tid] = s_morflag[tid];
            s_morflag[tid] = 0;
        }
        __syncthreads();

        // ====== warp-independent compacted chain: warp owns 2 rows end-to-end ======
        for (int base = 0; base < nact; base += 16) {
            const int slot = base + 2 * wid + p;
            const bool valid = slot < nact;
            const int ra = actk[slot & 31] & 31;
            if ((base + 2 * wid) < nact) {      // warp-uniform
                float4 uw, y1q;
                // u1 + r1 fused (shared A = YC row)
                mmC2<29, SYC>(sm + S_YC, sm + S_WU1, sm + S_WR1, ra, cb4, accU, accR);
                {
                    float2 u0 = unpack2(accU[0]), u1 = unpack2(accU[1]);
                    float2 rr0 = unpack2(accR[0]), rr1 = unpack2(accR[1]);
                    float4 hu, hr;
                    hu.x = fast_tanh(u0.x + sm[S_BU1 + cb4]);
                    hu.y = fast_tanh(u0.y + sm[S_BU1 + cb4 + 1]);
                    hu.z = fast_tanh(u1.x + sm[S_BU1 + cb4 + 2]);
                    hu.w = fast_tanh(u1.y + sm[S_BU1 + cb4 + 3]);
                    hr.x = fast_tanh(rr0.x + sm[S_BR1 + cb4]);
                    hr.y = fast_tanh(rr0.y + sm[S_BR1 + cb4 + 1]);
                    hr.z = fast_tanh(rr1.x + sm[S_BR1 + cb4 + 2]);
                    hr.w = fast_tanh(rr1.y + sm[S_BR1 + cb4 + 3]);
                    if (valid) {
                        *reinterpret_cast<float4*>(sm + S_H  + ra * SH2 + cb4) = hu;
                        *reinterpret_cast<float4*>(sm + S_HR + ra * SH2 + cb4) = hr;
                    }
                }
                __syncwarp();
                // u2 + r2 fused; u and y1 carried in registers
                mmC2d<16, SH2>(sm + S_H, sm + S_HR, sm + S_WU2, sm + S_WR2,
                               ra, cb4, accU, accR);
                {
                    float2 u0 = unpack2(accU[0]), u1 = unpack2(accU[1]);
                    float2 rr0 = unpack2(accR[0]), rr1 = unpack2(accR[1]);
                    uw.x = fast_sigm(u0.x + sm[S_BU2 + cb4]);
                    uw.y = fast_sigm(u0.y + sm[S_BU2 + cb4 + 1]);
                    uw.z = fast_sigm(u1.x + sm[S_BU2 + cb4 + 2]);
                    uw.w = fast_sigm(u1.y + sm[S_BU2 + cb4 + 3]);
                    float rg[4] = { fast_sigm(rr0.x + sm[S_BR2 + cb4]),
                                    fast_sigm(rr0.y + sm[S_BR2 + cb4 + 1]),
                                    fast_sigm(rr1.x + sm[S_BR2 + cb4 + 2]),
                                    fast_sigm(rr1.y + sm[S_BR2 + cb4 + 3]) };
                    // YC[0:64] still holds y1; read own quad, keep in registers
                    y1q = *reinterpret_cast<const float4*>(sm + S_YC + ra * SYC + cb4);
                    float4 yc;
                    yc.x = y1q.x * rg[0];
                    yc.y = y1q.y * rg[1];
                    yc.z = y1q.z * rg[2];
                    yc.w = y1q.w * rg[3];
                    if (valid) *reinterpret_cast<float4*>(sm + S_YC + ra * SYC + cb4) = yc;
                }
                __syncwarp();
                // n1: H_u = tanh(YC @ Wn1 + bn1)
                mmC<29, SYC>(sm + S_YC, sm + S_WN1, ra, cb4, accU);
                {
                    float2 v0 = unpack2(accU[0]), v1 = unpack2(accU[1]);
                    float4 hw;
                    hw.x = fast_tanh(v0.x + sm[S_BN1 + cb4]);
                    hw.y = fast_tanh(v0.y + sm[S_BN1 + cb4 + 1]);
                    hw.z = fast_tanh(v1.x + sm[S_BN1 + cb4 + 2]);
                    hw.w = fast_tanh(v1.y + sm[S_BN1 + cb4 + 3]);
                    if (valid) *reinterpret_cast<float4*>(sm + S_H + ra * SH2 + cb4) = hw;
                }
                __syncwarp();
                // n2 + blend (u and y1 from registers; only write Y when mask set)
                mmC<16, SH2>(sm + S_H, sm + S_WN2, ra, cb4, accU);
                {
                    const int mf = s_mflag[ra];
                    float2 v0 = unpack2(accU[0]), v1 = unpack2(accU[1]);
                    float ns[4] = { v0.x + sm[S_BN2 + cb4],
                                    v0.y + sm[S_BN2 + cb4 + 1],
                                    v1.x + sm[S_BN2 + cb4 + 2],
                                    v1.y + sm[S_BN2 + cb4 + 3] };
                    float uu[4]  = {uw.x, uw.y, uw.z, uw.w};
                    float y1v[4] = {y1q.x, y1q.y, y1q.z, y1q.w};
#pragma unroll
                    for (int cc = 0; cc < 4; ++cc) {
                        int j = cb4 + cc;
                        float ny = fmaf(1.f - uu[cc], ns[cc], uu[cc] * y1v[cc]);
                        if (valid && mf) sm[S_Y + j * SPC + ra] = ny;
                    }
                }
            }
        }
        __syncthreads();
    }

    // ---- write final prev_y ----
    for (int e = tid; e < 64 * RB; e += NTHR) {
        int j = e >> 5, r = e & 31;
        out_prevy[(size_t)(row_base + r) * 64 + j] = sm[S_Y + j * SPC + r];
    }

    // ---- fused gather: selected_state + time_intervals for this CTA's rows ----
    for (int i = tid; i < RB * (TT - 1); i += NTHR) {
        int r = i / (TT - 1);
        int t = i - r * (TT - 1);
        int b = row_base + r;
        int v0 = tsteps[(size_t)b * TT + t];
        int v1 = tsteps[(size_t)b * TT + t + 1];
        int inv = v0 < 0 ? 0 : (v0 > KK - 2 ? KK - 2 : v0);
        out_sel[(size_t)b * (TT - 1) + t] = g_vol[(size_t)b * KK + inv + 1];
        out_ti[(size_t)b * (TT - 1) + t]  = (float)(v1 - v0);
    }
}

extern "C" void kernel_launch(void* const* d_in, const int* in_sizes, int n_in,
                              void* d_out, int out_size) {
    const float* data = (const float*)d_in[0];
    const int*   ts   = (const int*)d_in[1];
    const float* Wu1 = (const float*)d_in[2];
    const float* bu1 = (const float*)d_in[3];
    const float* Wu2 = (const float*)d_in[4];
    const float* bu2 = (const float*)d_in[5];
    const float* Wr1 = (const float*)d_in[6];
    const float* br1 = (const float*)d_in[7];
    const float* Wr2 = (const float*)d_in[8];
    const float* br2 = (const float*)d_in[9];
    const float* Wn1 = (const float*)d_in[10];
    const float* bn1 = (const float*)d_in[11];
    const float* Wn2 = (const float*)d_in[12];
    const float* bn2 = (const float*)d_in[13];
    const float* Wo1 = (const float*)d_in[14];
    const float* bo1 = (const float*)d_in[15];
    const float* Wo2 = (const float*)d_in[16];
    const float* bo2 = (const float*)d_in[17];
    const float* Wd  = (const float*)d_in[18];
    const float* bd  = (const float*)d_in[19];

    float* out = (float*)d_out;
    float* out_prevy = out;                       // B*64
    float* out_sel   = out + (size_t)BB * LL;     // B*63
    float* out_ti    = out_sel + (size_t)BB * (TT - 1);

    cudaFuncSetAttribute(lobrm_main, cudaFuncAttributeMaxDynamicSharedMemorySize,
                         SMEM_BYTES);
    lobrm_main<<<BB / RB, NTHR, SMEM_BYTES>>>(
        data, ts, Wu1, bu1, Wu2, bu2, Wr1, br1, Wr2, br2,
        Wn1, bn1, Wn2, bn2, Wo1, bo1, Wo2, bo2, Wd, bd,
        out_prevy, out_sel, out_ti);
}